// round 14
// baseline (speedup 1.0000x reference)
#include <cuda_runtime.h>
#include <cuda_fp8.h>

// COAT Coat_quantize_bgn forward, group_size = 16.  FINAL (roofline-locked).
// x: [4, 4096, 4096] f32 (67108864 elems)
// out layout (concat, f32): [x passthrough (n)] [Q (n)] [Oscale (n/16)]
//
// Best-measured config across the full sweep (MLP 1/2/4/8, occ 23-79%,
// direction batching, predication, store placement, cache policy, 128b vs
// 256b accesses): TPB=256, SEG=4 float4/thread at block-coherent stride,
// unpredicated (16777216 float4 = 16384 blocks x 1024 exactly), interleaved
// .cs stores. ~117 us kernel = 784 MB @ ~6.5 TB/s, the confirmed achieved
// HBM ceiling for this 1-read : 2-write stream on GB300 (sm_103a).

#define COAT_E4M3_MAX 448.0f
#define SEG 4
#define TPB 256

__global__ void __launch_bounds__(TPB)
coat_quantize_kernel(const float4* __restrict__ x4,
                     float4* __restrict__ out_x4,
                     float4* __restrict__ out_q4,
                     float* __restrict__ out_s)
{
    int tid = threadIdx.x;
    int base = blockIdx.x * (TPB * SEG) + tid;

    // Front-batched loads: 4 independent LDG.128 in flight per thread.
    float4 v[SEG];
#pragma unroll
    for (int k = 0; k < SEG; k++)
        v[k] = __ldcs(&x4[base + k * TPB]);

    // Group amax (4 consecutive lanes = one group of 16) -> scale.
    float scale[SEG];
#pragma unroll
    for (int k = 0; k < SEG; k++) {
        float a = fmaxf(fmaxf(fabsf(v[k].x), fabsf(v[k].y)),
                        fmaxf(fabsf(v[k].z), fabsf(v[k].w)));
        a = fmaxf(a, __shfl_xor_sync(0xffffffffu, a, 1));
        a = fmaxf(a, __shfl_xor_sync(0xffffffffu, a, 2));
        scale[k] = (a == 0.0f) ? 1.0f : __fdiv_rn(a, COAT_E4M3_MAX);
    }

    // Quantize to e4m3 grid (RN, satfinite — matches XLA cast) and store.
#pragma unroll
    for (int k = 0; k < SEG; k++) {
        int i = base + k * TPB;
        float s = scale[k];
        float4 q;
        q.x = float(__nv_fp8_e4m3(__fdiv_rn(v[k].x, s)));
        q.y = float(__nv_fp8_e4m3(__fdiv_rn(v[k].y, s)));
        q.z = float(__nv_fp8_e4m3(__fdiv_rn(v[k].z, s)));
        q.w = float(__nv_fp8_e4m3(__fdiv_rn(v[k].w, s)));

        __stcs(&out_x4[i], v[k]);   // passthrough
        __stcs(&out_q4[i], q);      // quantized (fp8 grid, f32 view)
        if ((tid & 3) == 0)
            __stcs(&out_s[i >> 2], s);
    }
}

extern "C" void kernel_launch(void* const* d_in, const int* in_sizes, int n_in,
                              void* d_out, int out_size)
{
    const float* x = (const float*)d_in[0];
    int n = in_sizes[0];              // 67108864
    int n4 = n >> 2;                  // 16777216 float4

    float* out = (float*)d_out;
    float4* out_x4 = (float4*)out;               // [n]   passthrough
    float4* out_q4 = (float4*)(out + (size_t)n); // [n]   Q
    float*  out_s  = out + 2 * (size_t)n;        // [n/16] Oscale

    int per_block = TPB * SEG;                   // 1024
    int blocks = n4 / per_block;                 // 16384 (exact)
    coat_quantize_kernel<<<blocks, TPB>>>(
        (const float4*)x, out_x4, out_q4, out_s);
}

// round 15
// speedup vs baseline: 1.0063x; 1.0063x over previous
#include <cuda_runtime.h>
#include <cuda_fp8.h>

// COAT Coat_quantize_bgn forward, group_size = 16.  FINAL (roofline-locked).
// x: [4, 4096, 4096] f32 (67108864 elems)
// out layout (concat, f32): [x passthrough (n)] [Q (n)] [Oscale (n/16)]
//
// Best-measured config across the full sweep (MLP 1/2/4/8, occ 23-79%,
// direction batching, predication, store placement, cache policy, 128b vs
// 256b accesses): TPB=256, SEG=4 float4/thread at block-coherent stride,
// unpredicated (16777216 float4 = 16384 blocks x 1024 exactly), interleaved
// .cs stores. ~117 us kernel = 784 MB @ ~6.5 TB/s, the confirmed achieved
// HBM ceiling for this 1-read : 2-write stream on GB300 (sm_103a).

#define COAT_E4M3_MAX 448.0f
#define SEG 4
#define TPB 256

__global__ void __launch_bounds__(TPB)
coat_quantize_kernel(const float4* __restrict__ x4,
                     float4* __restrict__ out_x4,
                     float4* __restrict__ out_q4,
                     float* __restrict__ out_s)
{
    int tid = threadIdx.x;
    int base = blockIdx.x * (TPB * SEG) + tid;

    // Front-batched loads: 4 independent LDG.128 in flight per thread.
    float4 v[SEG];
#pragma unroll
    for (int k = 0; k < SEG; k++)
        v[k] = __ldcs(&x4[base + k * TPB]);

    // Group amax (4 consecutive lanes = one group of 16) -> scale.
    float scale[SEG];
#pragma unroll
    for (int k = 0; k < SEG; k++) {
        float a = fmaxf(fmaxf(fabsf(v[k].x), fabsf(v[k].y)),
                        fmaxf(fabsf(v[k].z), fabsf(v[k].w)));
        a = fmaxf(a, __shfl_xor_sync(0xffffffffu, a, 1));
        a = fmaxf(a, __shfl_xor_sync(0xffffffffu, a, 2));
        scale[k] = (a == 0.0f) ? 1.0f : __fdiv_rn(a, COAT_E4M3_MAX);
    }

    // Quantize to e4m3 grid (RN, satfinite — matches XLA cast) and store.
#pragma unroll
    for (int k = 0; k < SEG; k++) {
        int i = base + k * TPB;
        float s = scale[k];
        float4 q;
        q.x = float(__nv_fp8_e4m3(__fdiv_rn(v[k].x, s)));
        q.y = float(__nv_fp8_e4m3(__fdiv_rn(v[k].y, s)));
        q.z = float(__nv_fp8_e4m3(__fdiv_rn(v[k].z, s)));
        q.w = float(__nv_fp8_e4m3(__fdiv_rn(v[k].w, s)));

        __stcs(&out_x4[i], v[k]);   // passthrough
        __stcs(&out_q4[i], q);      // quantized (fp8 grid, f32 view)
        if ((tid & 3) == 0)
            __stcs(&out_s[i >> 2], s);
    }
}

extern "C" void kernel_launch(void* const* d_in, const int* in_sizes, int n_in,
                              void* d_out, int out_size)
{
    const float* x = (const float*)d_in[0];
    int n = in_sizes[0];              // 67108864
    int n4 = n >> 2;                  // 16777216 float4

    float* out = (float*)d_out;
    float4* out_x4 = (float4*)out;               // [n]   passthrough
    float4* out_q4 = (float4*)(out + (size_t)n); // [n]   Q
    float*  out_s  = out + 2 * (size_t)n;        // [n/16] Oscale

    int per_block = TPB * SEG;                   // 1024
    int blocks = n4 / per_block;                 // 16384 (exact)
    coat_quantize_kernel<<<blocks, TPB>>>(
        (const float4*)x, out_x4, out_q4, out_s);
}